// round 6
// baseline (speedup 1.0000x reference)
#include <cuda_runtime.h>
#include <cstdint>
#include <math.h>

// Problem constants
#define B_  2
#define T_  2048
#define C_  1024
#define H_  16
#define D_  64
#define BT_ (B_*T_)          // 4096
#define C3_ (3*C_)           // 3072

// Scratch (device globals: allocation-guard safe)
__device__ float g_qkv[BT_ * C3_];   // (B*T, 3C), stored tf32-rounded
__device__ float g_y[BT_ * C_];      // (B*T, C), stored tf32-rounded
__device__ float g_xr[BT_ * C_];     // x, tf32-rounded
__device__ float g_WT1[C3_ * C_];    // W_attn^T, tf32-rounded
__device__ float g_WT2[C_ * C_];     // W_proj^T, tf32-rounded

__device__ __forceinline__ float to_tf32(float f) {
    uint32_t u;
    asm("cvt.rna.tf32.f32 %0, %1;" : "=r"(u) : "f"(f));
    return __uint_as_float(u);
}

__device__ __forceinline__ void mma_tf32(float* d, const uint32_t* a, const uint32_t* b) {
    asm volatile(
        "mma.sync.aligned.m16n8k8.row.col.f32.tf32.tf32.f32 "
        "{%0,%1,%2,%3}, {%4,%5,%6,%7}, {%8,%9}, {%0,%1,%2,%3};"
        : "+f"(d[0]), "+f"(d[1]), "+f"(d[2]), "+f"(d[3])
        : "r"(a[0]), "r"(a[1]), "r"(a[2]), "r"(a[3]), "r"(b[0]), "r"(b[1]));
}

__device__ __forceinline__ uint32_t smem_u32(const void* p) {
    uint32_t a;
    asm("{ .reg .u64 t; cvta.to.shared.u64 t, %1; cvt.u32.u64 %0, t; }" : "=r"(a) : "l"(p));
    return a;
}
__device__ __forceinline__ void cp_async16(uint32_t saddr, const void* g) {
    asm volatile("cp.async.cg.shared.global [%0], [%1], 16;" :: "r"(saddr), "l"(g));
}
#define CP_COMMIT()  asm volatile("cp.async.commit_group;" ::: "memory")
#define CP_WAIT(n)   asm volatile("cp.async.wait_group %0;" :: "n"(n) : "memory")

// ============================================================================
// Elementwise tf32 rounding (vectorized): out[i] = tf32(in[i])
// ============================================================================
__global__ void round_tf32_kernel(const float* __restrict__ in, float* __restrict__ out)
{
    const int i = (blockIdx.x * blockDim.x + threadIdx.x) * 4;
    float4 v = *(const float4*)&in[i];
    v.x = to_tf32(v.x); v.y = to_tf32(v.y);
    v.z = to_tf32(v.z); v.w = to_tf32(v.w);
    *(float4*)&out[i] = v;
}

// ============================================================================
// Transpose + tf32-round: out[n][k] = tf32(in[k][n]).
// ============================================================================
__global__ void transpose_tf32_kernel(const float* __restrict__ in, float* __restrict__ out,
                                      int R, int Cc)
{
    __shared__ float tile[32][33];
    const int bx = blockIdx.x * 32;
    const int by = blockIdx.y * 32;
    #pragma unroll
    for (int j = 0; j < 32; j += 8)
        tile[threadIdx.y + j][threadIdx.x] = in[(size_t)(by + threadIdx.y + j) * Cc + bx + threadIdx.x];
    __syncthreads();
    #pragma unroll
    for (int j = 0; j < 32; j += 8)
        out[(size_t)(bx + threadIdx.y + j) * R + by + threadIdx.x] =
            to_tf32(tile[threadIdx.x][threadIdx.y + j]);
}

// ============================================================================
// tf32 mma.sync GEMM:  Cmat[M,N] = A[M,K] @ BT[N,K]^T + bias[N]
// Operands PRE-ROUNDED to tf32. cp.async 3-stage pipeline, BK=16,
// 256 threads, 128x128 tile, 8 warps x (64x32). roundOut: tf32-round result.
// ============================================================================
__global__ __launch_bounds__(256, 2) void gemm_mma_kernel(
    const float* __restrict__ A, const float* __restrict__ BT,
    const float* __restrict__ bias, float* __restrict__ Cmat,
    int M, int N, int K, int roundOut)
{
    __shared__ float As[3][4][128][4];   // [stage][kq][m][ic]  8KB/stage
    __shared__ float Bs[3][4][128][4];

    const int tid  = threadIdx.x;
    const int lane = tid & 31;
    const int warp = tid >> 5;
    const int wr = warp >> 2;
    const int wc = warp & 3;
    const int g  = lane >> 2;
    const int kc = lane & 3;

    const int m0 = blockIdx.y * 128;
    const int n0 = blockIdx.x * 128;

    const int lm  = tid >> 2;            // 0..63
    const int lkq = tid & 3;             // 0..3

    const uint32_t asb = smem_u32(&As[0][0][0][0]) + (uint32_t)(lkq * 2048 + lm * 16);
    const uint32_t bsb = smem_u32(&Bs[0][0][0][0]) + (uint32_t)(lkq * 2048 + lm * 16);

    float acc[4][4][4];
    #pragma unroll
    for (int mf = 0; mf < 4; mf++)
        #pragma unroll
        for (int nf = 0; nf < 4; nf++)
            #pragma unroll
            for (int r = 0; r < 4; r++) acc[mf][nf][r] = 0.f;

    const int nch = K >> 4;              // K/16

    // prologue: chunks 0,1 -> stages 0,1
    #pragma unroll
    for (int s = 0; s < 2; s++) {
        const int k0 = s << 4;
        #pragma unroll
        for (int it = 0; it < 2; it++) {
            const int m = lm + it * 64;
            cp_async16(asb + (uint32_t)(s * 8192 + it * 64 * 16), &A[(size_t)(m0 + m) * K + k0 + 4 * lkq]);
            cp_async16(bsb + (uint32_t)(s * 8192 + it * 64 * 16), &BT[(size_t)(n0 + m) * K + k0 + 4 * lkq]);
        }
        CP_COMMIT();
    }

    int cur = 0;
    for (int ic = 0; ic < nch; ic++) {
        CP_WAIT(1);
        __syncthreads();

        #pragma unroll
        for (int t = 0; t < 2; t++) {
            uint32_t bf[4][2];
            #pragma unroll
            for (int nf = 0; nf < 4; nf++) {
                const int n = wc * 32 + nf * 8 + g;
                bf[nf][0] = __float_as_uint(Bs[cur][2 * t + 0][n][kc]);
                bf[nf][1] = __float_as_uint(Bs[cur][2 * t + 1][n][kc]);
            }
            #pragma unroll
            for (int mf = 0; mf < 4; mf++) {
                const int m = wr * 64 + mf * 16 + g;
                uint32_t af[4];
                af[0] = __float_as_uint(As[cur][2 * t + 0][m][kc]);
                af[1] = __float_as_uint(As[cur][2 * t + 0][m + 8][kc]);
                af[2] = __float_as_uint(As[cur][2 * t + 1][m][kc]);
                af[3] = __float_as_uint(As[cur][2 * t + 1][m + 8][kc]);
                #pragma unroll
                for (int nf = 0; nf < 4; nf++)
                    mma_tf32(acc[mf][nf], af, bf[nf]);
            }
        }

        const int nc2 = ic + 2;
        if (nc2 < nch) {
            const int st = (cur + 2 >= 3) ? cur - 1 : cur + 2;
            const int k0 = nc2 << 4;
            #pragma unroll
            for (int it = 0; it < 2; it++) {
                const int m = lm + it * 64;
                cp_async16(asb + (uint32_t)(st * 8192 + it * 64 * 16), &A[(size_t)(m0 + m) * K + k0 + 4 * lkq]);
                cp_async16(bsb + (uint32_t)(st * 8192 + it * 64 * 16), &BT[(size_t)(n0 + m) * K + k0 + 4 * lkq]);
            }
        }
        CP_COMMIT();   // empty group when no loads keeps the wait count exact

        cur = (cur + 1 >= 3) ? 0 : cur + 1;
    }

    #pragma unroll
    for (int mf = 0; mf < 4; mf++) {
        const int row = m0 + wr * 64 + mf * 16 + g;
        #pragma unroll
        for (int nf = 0; nf < 4; nf++) {
            const int col = n0 + wc * 32 + nf * 8 + kc * 2;
            const float b0 = bias[col];
            const float b1 = bias[col + 1];
            float2 o0 = { acc[mf][nf][0] + b0, acc[mf][nf][1] + b1 };
            float2 o1 = { acc[mf][nf][2] + b0, acc[mf][nf][3] + b1 };
            if (roundOut) {
                o0.x = to_tf32(o0.x); o0.y = to_tf32(o0.y);
                o1.x = to_tf32(o1.x); o1.y = to_tf32(o1.y);
            }
            *(float2*)&Cmat[(size_t)row * N + col] = o0;
            *(float2*)&Cmat[(size_t)(row + 8) * N + col] = o1;
        }
    }
}

// ============================================================================
// Flash attention (causal), tf32 mma.sync, cp.async double-buffered K/V.
// Inputs in g_qkv are already tf32-rounded -> no cvt in the mainloop.
// ============================================================================
#define KS_STRIDE 68
#define VS_STRIDE 72
#define PS_STRIDE 36

__global__ __launch_bounds__(128) void attn_mma_kernel(const float* __restrict__ amask)
{
    __shared__ __align__(16) float Ks[2][32 * KS_STRIDE];
    __shared__ __align__(16) float Vs[2][32 * VS_STRIDE];
    __shared__ __align__(16) float Ps[64 * PS_STRIDE];
    __shared__ float Ams[2][32];

    const int qt = (gridDim.x - 1) - blockIdx.x;   // heavy CTAs first
    const int hh = blockIdx.y;
    const int bb = blockIdx.z;
    const int tid = threadIdx.x;
    const int lane = tid & 31;
    const int w = tid >> 5;
    const int r = lane >> 2;
    const int c = lane & 3;
    const int qbase = qt * 64;
    const int qlo = qbase + w * 16;

    const uint32_t ksb = smem_u32(&Ks[0][0]);
    const uint32_t vsb = smem_u32(&Vs[0][0]);

    // --- stage Q into the Ks region (values already tf32) ---
    float* Qstage = &Ks[0][0];
    for (int i = tid; i < 64 * 16; i += 128) {
        const int row = i >> 4;
        const int c4 = (i & 15) * 4;
        float4 v = *(const float4*)&g_qkv[(size_t)(bb * T_ + qbase + row) * C3_ + hh * D_ + c4];
        *(float4*)&Qstage[row * KS_STRIDE + c4] = v;
    }
    __syncthreads();

    uint32_t qa[8][4];
    #pragma unroll
    for (int kf = 0; kf < 8; kf++) {
        const int row = w * 16 + r;
        const int col = kf * 8 + c;
        qa[kf][0] = __float_as_uint(Qstage[row * KS_STRIDE + col]);
        qa[kf][1] = __float_as_uint(Qstage[(row + 8) * KS_STRIDE + col]);
        qa[kf][2] = __float_as_uint(Qstage[row * KS_STRIDE + col + 4]);
        qa[kf][3] = __float_as_uint(Qstage[(row + 8) * KS_STRIDE + col + 4]);
    }
    __syncthreads();

    const int nkt = 2 * qt + 2;

    // --- prologue: tile 0 -> buf 0 ---
    {
        const size_t rb = (size_t)(bb * T_) * C3_ + hh * D_;
        for (int idx = tid; idx < 512; idx += 128) {
            const int row = idx >> 4;
            const int c4 = (idx & 15) * 4;
            const float* gk = &g_qkv[rb + (size_t)row * C3_ + C_ + c4];
            cp_async16(ksb + (uint32_t)(row * KS_STRIDE + c4) * 4u, gk);
            cp_async16(vsb + (uint32_t)(row * VS_STRIDE + c4) * 4u, gk + C_);
        }
        if (tid < 32) Ams[0][tid] = amask[bb * T_ + tid];
        CP_COMMIT();
    }

    float o[8][4];
    #pragma unroll
    for (int nb = 0; nb < 8; nb++)
        #pragma unroll
        for (int j = 0; j < 4; j++) o[nb][j] = 0.f;
    float mrow[2] = { -INFINITY, -INFINITY };
    float lrow[2] = { 0.f, 0.f };

    for (int kt = 0; kt < nkt; kt++) {
        const int buf = kt & 1;
        const int kbase = kt * 32;
        const bool more = (kt + 1) < nkt;

        if (more) {
            const int nb2 = buf ^ 1;
            const size_t rb = (size_t)(bb * T_ + kbase + 32) * C3_ + hh * D_;
            const uint32_t kdst = ksb + (uint32_t)(nb2 * 32 * KS_STRIDE) * 4u;
            const uint32_t vdst = vsb + (uint32_t)(nb2 * 32 * VS_STRIDE) * 4u;
            for (int idx = tid; idx < 512; idx += 128) {
                const int row = idx >> 4;
                const int c4 = (idx & 15) * 4;
                const float* gk = &g_qkv[rb + (size_t)row * C3_ + C_ + c4];
                cp_async16(kdst + (uint32_t)(row * KS_STRIDE + c4) * 4u, gk);
                cp_async16(vdst + (uint32_t)(row * VS_STRIDE + c4) * 4u, gk + C_);
            }
            if (tid < 32) Ams[nb2][tid] = amask[bb * T_ + kbase + 32 + tid];
            CP_COMMIT();
            CP_WAIT(1);
        } else {
            CP_WAIT(0);
        }
        __syncthreads();

        const bool act = (kbase <= qlo + 15);
        if (act) {
            const float* ksB = &Ks[buf][0];
            const float* vsB = &Vs[buf][0];

            // --- S = Q K^T ---
            float s[4][4];
            #pragma unroll
            for (int nb = 0; nb < 4; nb++)
                #pragma unroll
                for (int j = 0; j < 4; j++) s[nb][j] = 0.f;
            #pragma unroll
            for (int kf = 0; kf < 8; kf++) {
                #pragma unroll
                for (int nb = 0; nb < 4; nb++) {
                    uint32_t bf[2];
                    bf[0] = __float_as_uint(ksB[(nb * 8 + r) * KS_STRIDE + kf * 8 + c]);
                    bf[1] = __float_as_uint(ksB[(nb * 8 + r) * KS_STRIDE + kf * 8 + c + 4]);
                    mma_tf32(s[nb], qa[kf], bf);
                }
            }

            // --- scale + masks ---
            const bool needmask = (kbase + 31 > qlo);
            #pragma unroll
            for (int nb = 0; nb < 4; nb++) {
                const float a0 = Ams[buf][nb * 8 + 2 * c];
                const float a1 = Ams[buf][nb * 8 + 2 * c + 1];
                s[nb][0] = s[nb][0] * 0.125f + a0;
                s[nb][1] = s[nb][1] * 0.125f + a1;
                s[nb][2] = s[nb][2] * 0.125f + a0;
                s[nb][3] = s[nb][3] * 0.125f + a1;
                if (needmask) {
                    const int kc0 = kbase + nb * 8 + 2 * c;
                    const int q0 = qlo + r;
                    if (kc0 > q0)         s[nb][0] = -INFINITY;
                    if (kc0 + 1 > q0)     s[nb][1] = -INFINITY;
                    if (kc0 > q0 + 8)     s[nb][2] = -INFINITY;
                    if (kc0 + 1 > q0 + 8) s[nb][3] = -INFINITY;
                }
            }

            __syncwarp();

            // --- online softmax ---
            #pragma unroll
            for (int hf = 0; hf < 2; hf++) {
                float mx = -INFINITY;
                #pragma unroll
                for (int nb = 0; nb < 4; nb++)
                    mx = fmaxf(mx, fmaxf(s[nb][2 * hf], s[nb][2 * hf + 1]));
                mx = fmaxf(mx, __shfl_xor_sync(0xffffffffu, mx, 1));
                mx = fmaxf(mx, __shfl_xor_sync(0xffffffffu, mx, 2));
                const float mnew = fmaxf(mrow[hf], mx);
                const float corr = __expf(mrow[hf] - mnew);
                float sum = 0.f;
                const int prow = w * 16 + r + 8 * hf;
                #pragma unroll
                for (int nb = 0; nb < 4; nb++) {
                    const float p0 = __expf(s[nb][2 * hf] - mnew);
                    const float p1 = __expf(s[nb][2 * hf + 1] - mnew);
                    sum += p0 + p1;
                    Ps[prow * PS_STRIDE + nb * 8 + 2 * c]     = to_tf32(p0);
                    Ps[prow * PS_STRIDE + nb * 8 + 2 * c + 1] = to_tf32(p1);
                }
                sum += __shfl_xor_sync(0xffffffffu, sum, 1);
                sum += __shfl_xor_sync(0xffffffffu, sum, 2);
                lrow[hf] = lrow[hf] * corr + sum;
                mrow[hf] = mnew;
                #pragma unroll
                for (int nb = 0; nb < 8; nb++) {
                    o[nb][2 * hf]     *= corr;
                    o[nb][2 * hf + 1] *= corr;
                }
            }
            __syncwarp();

            // --- O += P V ---
            #pragma unroll
            for (int kf = 0; kf < 4; kf++) {
                uint32_t pa[4];
                const int prow = w * 16 + r;
                pa[0] = __float_as_uint(Ps[prow * PS_STRIDE + kf * 8 + c]);
                pa[1] = __float_as_uint(Ps[(prow + 8) * PS_STRIDE + kf * 8 + c]);
                pa[2] = __float_as_uint(Ps[prow * PS_STRIDE + kf * 8 + c + 4]);
                pa[3] = __float_as_uint(Ps[(prow + 8) * PS_STRIDE + kf * 8 + c + 4]);
                #pragma unroll
                for (int nb = 0; nb < 8; nb++) {
                    uint32_t bf[2];
                    bf[0] = __float_as_uint(vsB[(kf * 8 + c) * VS_STRIDE + nb * 8 + r]);
                    bf[1] = __float_as_uint(vsB[(kf * 8 + c + 4) * VS_STRIDE + nb * 8 + r]);
                    mma_tf32(o[nb], pa, bf);
                }
            }
        }
        __syncthreads();
    }

    // --- epilogue: write g_y tf32-rounded (proj GEMM reads it pre-rounded) ---
    const float inv0 = 1.f / lrow[0];
    const float inv1 = 1.f / lrow[1];
    const int row0 = bb * T_ + qbase + w * 16 + r;
    #pragma unroll
    for (int nb = 0; nb < 8; nb++) {
        const int col = hh * D_ + nb * 8 + 2 * c;
        float2 v0 = { to_tf32(o[nb][0] * inv0), to_tf32(o[nb][1] * inv0) };
        float2 v1 = { to_tf32(o[nb][2] * inv1), to_tf32(o[nb][3] * inv1) };
        *(float2*)&g_y[(size_t)row0 * C_ + col] = v0;
        *(float2*)&g_y[(size_t)(row0 + 8) * C_ + col] = v1;
    }
}

// ----------------------------------------------------------------------------
// Launch.  Inputs: 0 x, 1 attention_mask, 2 attention_bias, 3 W_attn,
//                  4 b_attn, 5 W_proj, 6 b_proj
// ----------------------------------------------------------------------------
extern "C" void kernel_launch(void* const* d_in, const int* in_sizes, int n_in,
                              void* d_out, int out_size)
{
    (void)in_sizes; (void)n_in; (void)out_size;
    const float* x      = (const float*)d_in[0];
    const float* amask  = (const float*)d_in[1];
    const float* W_attn = (const float*)d_in[3];
    const float* b_attn = (const float*)d_in[4];
    const float* W_proj = (const float*)d_in[5];
    const float* b_proj = (const float*)d_in[6];
    float* out = (float*)d_out;

    float *qkv_ptr = nullptr, *y_ptr = nullptr, *xr = nullptr, *wt1 = nullptr, *wt2 = nullptr;
    cudaGetSymbolAddress((void**)&qkv_ptr, g_qkv);
    cudaGetSymbolAddress((void**)&y_ptr, g_y);
    cudaGetSymbolAddress((void**)&xr, g_xr);
    cudaGetSymbolAddress((void**)&wt1, g_WT1);
    cudaGetSymbolAddress((void**)&wt2, g_WT2);

    // 0) Pre-round / pre-transpose operands
    round_tf32_kernel<<<(BT_ * C_) / (256 * 4), 256>>>(x, xr);
    transpose_tf32_kernel<<<dim3(C3_ / 32, C_ / 32), dim3(32, 8)>>>(W_attn, wt1, C_, C3_);
    transpose_tf32_kernel<<<dim3(C_ / 32, C_ / 32), dim3(32, 8)>>>(W_proj, wt2, C_, C_);

    // 1) QKV projection (output tf32-rounded for attention)
    gemm_mma_kernel<<<dim3(C3_ / 128, BT_ / 128), 256>>>(xr, wt1, b_attn, qkv_ptr, BT_, C3_, C_, 1);

    // 2) Causal flash attention (tensor cores, pipelined)
    attn_mma_kernel<<<dim3(T_ / 64, H_, B_), 128>>>(amask);

    // 3) Output projection (fp32 output)
    gemm_mma_kernel<<<dim3(C_ / 128, BT_ / 128), 256>>>(y_ptr, wt2, b_proj, out, BT_, C_, C_, 0);
}

// round 8
// speedup vs baseline: 1.0090x; 1.0090x over previous
#include <cuda_runtime.h>
#include <cstdint>
#include <math.h>

// Problem constants
#define B_  2
#define T_  2048
#define C_  1024
#define H_  16
#define D_  64
#define BT_ (B_*T_)          // 4096
#define C3_ (3*C_)           // 3072

// Scratch (device globals: allocation-guard safe)
__device__ float g_qkv[BT_ * C3_];   // (B*T, 3C), stored tf32-rounded
__device__ float g_y[BT_ * C_];      // (B*T, C), stored tf32-rounded
__device__ float g_xr[BT_ * C_];     // x, tf32-rounded
__device__ float g_WT1[C3_ * C_];    // W_attn^T, tf32-rounded
__device__ float g_WT2[C_ * C_];     // W_proj^T, tf32-rounded

__device__ __forceinline__ float to_tf32(float f) {
    uint32_t u;
    asm("cvt.rna.tf32.f32 %0, %1;" : "=r"(u) : "f"(f));
    return __uint_as_float(u);
}

__device__ __forceinline__ void mma_tf32(float* d, const uint32_t* a, const uint32_t* b) {
    asm volatile(
        "mma.sync.aligned.m16n8k8.row.col.f32.tf32.tf32.f32 "
        "{%0,%1,%2,%3}, {%4,%5,%6,%7}, {%8,%9}, {%0,%1,%2,%3};"
        : "+f"(d[0]), "+f"(d[1]), "+f"(d[2]), "+f"(d[3])
        : "r"(a[0]), "r"(a[1]), "r"(a[2]), "r"(a[3]), "r"(b[0]), "r"(b[1]));
}

__device__ __forceinline__ uint32_t smem_u32(const void* p) {
    uint32_t a;
    asm("{ .reg .u64 t; cvta.to.shared.u64 t, %1; cvt.u32.u64 %0, t; }" : "=r"(a) : "l"(p));
    return a;
}
__device__ __forceinline__ void cp_async16(uint32_t saddr, const void* g) {
    asm volatile("cp.async.cg.shared.global [%0], [%1], 16;" :: "r"(saddr), "l"(g));
}
#define CP_COMMIT()  asm volatile("cp.async.commit_group;" ::: "memory")
#define CP_WAIT(n)   asm volatile("cp.async.wait_group %0;" :: "n"(n) : "memory")

// ============================================================================
// Elementwise tf32 rounding (vectorized): out[i] = tf32(in[i])
// ============================================================================
__global__ void round_tf32_kernel(const float* __restrict__ in, float* __restrict__ out)
{
    const int i = (blockIdx.x * blockDim.x + threadIdx.x) * 4;
    float4 v = *(const float4*)&in[i];
    v.x = to_tf32(v.x); v.y = to_tf32(v.y);
    v.z = to_tf32(v.z); v.w = to_tf32(v.w);
    *(float4*)&out[i] = v;
}

// ============================================================================
// Transpose + tf32-round: out[n][k] = tf32(in[k][n]).
// ============================================================================
__global__ void transpose_tf32_kernel(const float* __restrict__ in, float* __restrict__ out,
                                      int R, int Cc)
{
    __shared__ float tile[32][33];
    const int bx = blockIdx.x * 32;
    const int by = blockIdx.y * 32;
    #pragma unroll
    for (int j = 0; j < 32; j += 8)
        tile[threadIdx.y + j][threadIdx.x] = in[(size_t)(by + threadIdx.y + j) * Cc + bx + threadIdx.x];
    __syncthreads();
    #pragma unroll
    for (int j = 0; j < 32; j += 8)
        out[(size_t)(bx + threadIdx.y + j) * R + by + threadIdx.x] =
            to_tf32(tile[threadIdx.x][threadIdx.y + j]);
}

// ============================================================================
// tf32 mma.sync GEMM:  Cmat[M,N] = A[M,K] @ BT[N,K]^T + bias[N]
// Operands pre-rounded tf32. cp.async 4-stage pipeline (64KB dynamic smem),
// wait distance 2 chunks. BK=16, 256 threads, 128x128 tile, 8 warps x (64x32).
// Smem float layout: A stage s at s*2048 floats (8KB/stage),
//                    B stage s at 8192 + s*2048 floats,
// each stage [kq(4)][row(128)][ic(4)].
// ============================================================================
#define GEMM_STAGES 4
#define GEMM_SMEM_BYTES (GEMM_STAGES * 16384)

__global__ __launch_bounds__(256, 2) void gemm_mma_kernel(
    const float* __restrict__ A, const float* __restrict__ BT,
    const float* __restrict__ bias, float* __restrict__ Cmat,
    int M, int N, int K, int roundOut)
{
    extern __shared__ __align__(16) float sm[];

    const int tid  = threadIdx.x;
    const int lane = tid & 31;
    const int warp = tid >> 5;
    const int wr = warp >> 2;
    const int wc = warp & 3;
    const int g  = lane >> 2;
    const int kc = lane & 3;

    const int m0 = blockIdx.y * 128;
    const int n0 = blockIdx.x * 128;

    const int lm  = tid >> 2;            // 0..63
    const int lkq = tid & 3;             // 0..3

    // cp.async store base addresses (bytes); per-stage stride = 8192 bytes
    const uint32_t smb = smem_u32(sm);
    const uint32_t asb = smb + (uint32_t)(lkq * 2048 + lm * 16);
    const uint32_t bsb = smb + 32768u + (uint32_t)(lkq * 2048 + lm * 16);

    float acc[4][4][4];
    #pragma unroll
    for (int mf = 0; mf < 4; mf++)
        #pragma unroll
        for (int nf = 0; nf < 4; nf++)
            #pragma unroll
            for (int r = 0; r < 4; r++) acc[mf][nf][r] = 0.f;

    const int nch = K >> 4;              // K/16

    // prologue: chunks 0..2 -> stages 0..2
    #pragma unroll
    for (int s = 0; s < GEMM_STAGES - 1; s++) {
        const int k0 = s << 4;
        #pragma unroll
        for (int it = 0; it < 2; it++) {
            const int m = lm + it * 64;
            cp_async16(asb + (uint32_t)(s * 8192 + it * 1024), &A[(size_t)(m0 + m) * K + k0 + 4 * lkq]);
            cp_async16(bsb + (uint32_t)(s * 8192 + it * 1024), &BT[(size_t)(n0 + m) * K + k0 + 4 * lkq]);
        }
        CP_COMMIT();
    }

    for (int ic = 0; ic < nch; ic++) {
        CP_WAIT(2);          // chunk ic complete; ic+1, ic+2 may be in flight
        __syncthreads();

        const int cur = ic & 3;
        const float* As = &sm[cur * 2048];            // [kq][128][4]
        const float* Bs = &sm[8192 + cur * 2048];

        #pragma unroll
        for (int t = 0; t < 2; t++) {
            uint32_t bf[4][2];
            #pragma unroll
            for (int nf = 0; nf < 4; nf++) {
                const int n = wc * 32 + nf * 8 + g;
                bf[nf][0] = __float_as_uint(Bs[(2 * t + 0) * 512 + n * 4 + kc]);
                bf[nf][1] = __float_as_uint(Bs[(2 * t + 1) * 512 + n * 4 + kc]);
            }
            #pragma unroll
            for (int mf = 0; mf < 4; mf++) {
                const int m = wr * 64 + mf * 16 + g;
                uint32_t af[4];
                af[0] = __float_as_uint(As[(2 * t + 0) * 512 + m * 4 + kc]);
                af[1] = __float_as_uint(As[(2 * t + 0) * 512 + (m + 8) * 4 + kc]);
                af[2] = __float_as_uint(As[(2 * t + 1) * 512 + m * 4 + kc]);
                af[3] = __float_as_uint(As[(2 * t + 1) * 512 + (m + 8) * 4 + kc]);
                #pragma unroll
                for (int nf = 0; nf < 4; nf++)
                    mma_tf32(acc[mf][nf], af, bf[nf]);
            }
        }

        // issue chunk ic+3 into stage (ic+3)&3 (= stage of chunk ic-1, now free)
        const int nc3 = ic + 3;
        if (nc3 < nch) {
            const int st = nc3 & 3;
            const int k0 = nc3 << 4;
            #pragma unroll
            for (int it = 0; it < 2; it++) {
                const int m = lm + it * 64;
                cp_async16(asb + (uint32_t)(st * 8192 + it * 1024), &A[(size_t)(m0 + m) * K + k0 + 4 * lkq]);
                cp_async16(bsb + (uint32_t)(st * 8192 + it * 1024), &BT[(size_t)(n0 + m) * K + k0 + 4 * lkq]);
            }
        }
        CP_COMMIT();   // empty group when no loads keeps the wait count exact
    }

    #pragma unroll
    for (int mf = 0; mf < 4; mf++) {
        const int row = m0 + wr * 64 + mf * 16 + g;
        #pragma unroll
        for (int nf = 0; nf < 4; nf++) {
            const int col = n0 + wc * 32 + nf * 8 + kc * 2;
            const float b0 = bias[col];
            const float b1 = bias[col + 1];
            float2 o0 = { acc[mf][nf][0] + b0, acc[mf][nf][1] + b1 };
            float2 o1 = { acc[mf][nf][2] + b0, acc[mf][nf][3] + b1 };
            if (roundOut) {
                o0.x = to_tf32(o0.x); o0.y = to_tf32(o0.y);
                o1.x = to_tf32(o1.x); o1.y = to_tf32(o1.y);
            }
            *(float2*)&Cmat[(size_t)row * N + col] = o0;
            *(float2*)&Cmat[(size_t)(row + 8) * N + col] = o1;
        }
    }
}

// ============================================================================
// Flash attention (causal), tf32 mma.sync, cp.async double-buffered K/V.
// Inputs in g_qkv are already tf32-rounded -> no cvt in the mainloop.
// ============================================================================
#define KS_STRIDE 68
#define VS_STRIDE 72
#define PS_STRIDE 36

__global__ __launch_bounds__(128) void attn_mma_kernel(const float* __restrict__ amask)
{
    __shared__ __align__(16) float Ks[2][32 * KS_STRIDE];
    __shared__ __align__(16) float Vs[2][32 * VS_STRIDE];
    __shared__ __align__(16) float Ps[64 * PS_STRIDE];
    __shared__ float Ams[2][32];

    const int qt = (gridDim.x - 1) - blockIdx.x;   // heavy CTAs first
    const int hh = blockIdx.y;
    const int bb = blockIdx.z;
    const int tid = threadIdx.x;
    const int lane = tid & 31;
    const int w = tid >> 5;
    const int r = lane >> 2;
    const int c = lane & 3;
    const int qbase = qt * 64;
    const int qlo = qbase + w * 16;

    const uint32_t ksb = smem_u32(&Ks[0][0]);
    const uint32_t vsb = smem_u32(&Vs[0][0]);

    // --- stage Q into the Ks region (values already tf32) ---
    float* Qstage = &Ks[0][0];
    for (int i = tid; i < 64 * 16; i += 128) {
        const int row = i >> 4;
        const int c4 = (i & 15) * 4;
        float4 v = *(const float4*)&g_qkv[(size_t)(bb * T_ + qbase + row) * C3_ + hh * D_ + c4];
        *(float4*)&Qstage[row * KS_STRIDE + c4] = v;
    }
    __syncthreads();

    uint32_t qa[8][4];
    #pragma unroll
    for (int kf = 0; kf < 8; kf++) {
        const int row = w * 16 + r;
        const int col = kf * 8 + c;
        qa[kf][0] = __float_as_uint(Qstage[row * KS_STRIDE + col]);
        qa[kf][1] = __float_as_uint(Qstage[(row + 8) * KS_STRIDE + col]);
        qa[kf][2] = __float_as_uint(Qstage[row * KS_STRIDE + col + 4]);
        qa[kf][3] = __float_as_uint(Qstage[(row + 8) * KS_STRIDE + col + 4]);
    }
    __syncthreads();

    const int nkt = 2 * qt + 2;

    // --- prologue: tile 0 -> buf 0 ---
    {
        const size_t rb = (size_t)(bb * T_) * C3_ + hh * D_;
        for (int idx = tid; idx < 512; idx += 128) {
            const int row = idx >> 4;
            const int c4 = (idx & 15) * 4;
            const float* gk = &g_qkv[rb + (size_t)row * C3_ + C_ + c4];
            cp_async16(ksb + (uint32_t)(row * KS_STRIDE + c4) * 4u, gk);
            cp_async16(vsb + (uint32_t)(row * VS_STRIDE + c4) * 4u, gk + C_);
        }
        if (tid < 32) Ams[0][tid] = amask[bb * T_ + tid];
        CP_COMMIT();
    }

    float o[8][4];
    #pragma unroll
    for (int nb = 0; nb < 8; nb++)
        #pragma unroll
        for (int j = 0; j < 4; j++) o[nb][j] = 0.f;
    float mrow[2] = { -INFINITY, -INFINITY };
    float lrow[2] = { 0.f, 0.f };

    for (int kt = 0; kt < nkt; kt++) {
        const int buf = kt & 1;
        const int kbase = kt * 32;
        const bool more = (kt + 1) < nkt;

        if (more) {
            const int nb2 = buf ^ 1;
            const size_t rb = (size_t)(bb * T_ + kbase + 32) * C3_ + hh * D_;
            const uint32_t kdst = ksb + (uint32_t)(nb2 * 32 * KS_STRIDE) * 4u;
            const uint32_t vdst = vsb + (uint32_t)(nb2 * 32 * VS_STRIDE) * 4u;
            for (int idx = tid; idx < 512; idx += 128) {
                const int row = idx >> 4;
                const int c4 = (idx & 15) * 4;
                const float* gk = &g_qkv[rb + (size_t)row * C3_ + C_ + c4];
                cp_async16(kdst + (uint32_t)(row * KS_STRIDE + c4) * 4u, gk);
                cp_async16(vdst + (uint32_t)(row * VS_STRIDE + c4) * 4u, gk + C_);
            }
            if (tid < 32) Ams[nb2][tid] = amask[bb * T_ + kbase + 32 + tid];
            CP_COMMIT();
            CP_WAIT(1);
        } else {
            CP_WAIT(0);
        }
        __syncthreads();

        const bool act = (kbase <= qlo + 15);
        if (act) {
            const float* ksB = &Ks[buf][0];
            const float* vsB = &Vs[buf][0];

            // --- S = Q K^T ---
            float s[4][4];
            #pragma unroll
            for (int nb = 0; nb < 4; nb++)
                #pragma unroll
                for (int j = 0; j < 4; j++) s[nb][j] = 0.f;
            #pragma unroll
            for (int kf = 0; kf < 8; kf++) {
                #pragma unroll
                for (int nb = 0; nb < 4; nb++) {
                    uint32_t bf[2];
                    bf[0] = __float_as_uint(ksB[(nb * 8 + r) * KS_STRIDE + kf * 8 + c]);
                    bf[1] = __float_as_uint(ksB[(nb * 8 + r) * KS_STRIDE + kf * 8 + c + 4]);
                    mma_tf32(s[nb], qa[kf], bf);
                }
            }

            // --- scale + masks ---
            const bool needmask = (kbase + 31 > qlo);
            #pragma unroll
            for (int nb = 0; nb < 4; nb++) {
                const float a0 = Ams[buf][nb * 8 + 2 * c];
                const float a1 = Ams[buf][nb * 8 + 2 * c + 1];
                s[nb][0] = s[nb][0] * 0.125f + a0;
                s[nb][1] = s[nb][1] * 0.125f + a1;
                s[nb][2] = s[nb][2] * 0.125f + a0;
                s[nb][3] = s[nb][3] * 0.125f + a1;
                if (needmask) {
                    const int kc0 = kbase + nb * 8 + 2 * c;
                    const int q0 = qlo + r;
                    if (kc0 > q0)         s[nb][0] = -INFINITY;
                    if (kc0 + 1 > q0)     s[nb][1] = -INFINITY;
                    if (kc0 > q0 + 8)     s[nb][2] = -INFINITY;
                    if (kc0 + 1 > q0 + 8) s[nb][3] = -INFINITY;
                }
            }

            __syncwarp();

            // --- online softmax ---
            #pragma unroll
            for (int hf = 0; hf < 2; hf++) {
                float mx = -INFINITY;
                #pragma unroll
                for (int nb = 0; nb < 4; nb++)
                    mx = fmaxf(mx, fmaxf(s[nb][2 * hf], s[nb][2 * hf + 1]));
                mx = fmaxf(mx, __shfl_xor_sync(0xffffffffu, mx, 1));
                mx = fmaxf(mx, __shfl_xor_sync(0xffffffffu, mx, 2));
                const float mnew = fmaxf(mrow[hf], mx);
                const float corr = __expf(mrow[hf] - mnew);
                float sum = 0.f;
                const int prow = w * 16 + r + 8 * hf;
                #pragma unroll
                for (int nb = 0; nb < 4; nb++) {
                    const float p0 = __expf(s[nb][2 * hf] - mnew);
                    const float p1 = __expf(s[nb][2 * hf + 1] - mnew);
                    sum += p0 + p1;
                    Ps[prow * PS_STRIDE + nb * 8 + 2 * c]     = to_tf32(p0);
                    Ps[prow * PS_STRIDE + nb * 8 + 2 * c + 1] = to_tf32(p1);
                }
                sum += __shfl_xor_sync(0xffffffffu, sum, 1);
                sum += __shfl_xor_sync(0xffffffffu, sum, 2);
                lrow[hf] = lrow[hf] * corr + sum;
                mrow[hf] = mnew;
                #pragma unroll
                for (int nb = 0; nb < 8; nb++) {
                    o[nb][2 * hf]     *= corr;
                    o[nb][2 * hf + 1] *= corr;
                }
            }
            __syncwarp();

            // --- O += P V ---
            #pragma unroll
            for (int kf = 0; kf < 4; kf++) {
                uint32_t pa[4];
                const int prow = w * 16 + r;
                pa[0] = __float_as_uint(Ps[prow * PS_STRIDE + kf * 8 + c]);
                pa[1] = __float_as_uint(Ps[(prow + 8) * PS_STRIDE + kf * 8 + c]);
                pa[2] = __float_as_uint(Ps[prow * PS_STRIDE + kf * 8 + c + 4]);
                pa[3] = __float_as_uint(Ps[(prow + 8) * PS_STRIDE + kf * 8 + c + 4]);
                #pragma unroll
                for (int nb = 0; nb < 8; nb++) {
                    uint32_t bf[2];
                    bf[0] = __float_as_uint(vsB[(kf * 8 + c) * VS_STRIDE + nb * 8 + r]);
                    bf[1] = __float_as_uint(vsB[(kf * 8 + c + 4) * VS_STRIDE + nb * 8 + r]);
                    mma_tf32(o[nb], pa, bf);
                }
            }
        }
        __syncthreads();
    }

    // --- epilogue: write g_y tf32-rounded (proj GEMM reads it pre-rounded) ---
    const float inv0 = 1.f / lrow[0];
    const float inv1 = 1.f / lrow[1];
    const int row0 = bb * T_ + qbase + w * 16 + r;
    #pragma unroll
    for (int nb = 0; nb < 8; nb++) {
        const int col = hh * D_ + nb * 8 + 2 * c;
        float2 v0 = { to_tf32(o[nb][0] * inv0), to_tf32(o[nb][1] * inv0) };
        float2 v1 = { to_tf32(o[nb][2] * inv1), to_tf32(o[nb][3] * inv1) };
        *(float2*)&g_y[(size_t)row0 * C_ + col] = v0;
        *(float2*)&g_y[(size_t)(row0 + 8) * C_ + col] = v1;
    }
}

// ----------------------------------------------------------------------------
// Launch.  Inputs: 0 x, 1 attention_mask, 2 attention_bias, 3 W_attn,
//                  4 b_attn, 5 W_proj, 6 b_proj
// ----------------------------------------------------------------------------
extern "C" void kernel_launch(void* const* d_in, const int* in_sizes, int n_in,
                              void* d_out, int out_size)
{
    (void)in_sizes; (void)n_in; (void)out_size;
    const float* x      = (const float*)d_in[0];
    const float* amask  = (const float*)d_in[1];
    const float* W_attn = (const float*)d_in[3];
    const float* b_attn = (const float*)d_in[4];
    const float* W_proj = (const float*)d_in[5];
    const float* b_proj = (const float*)d_in[6];
    float* out = (float*)d_out;

    float *qkv_ptr = nullptr, *y_ptr = nullptr, *xr = nullptr, *wt1 = nullptr, *wt2 = nullptr;
    cudaGetSymbolAddress((void**)&qkv_ptr, g_qkv);
    cudaGetSymbolAddress((void**)&y_ptr, g_y);
    cudaGetSymbolAddress((void**)&xr, g_xr);
    cudaGetSymbolAddress((void**)&wt1, g_WT1);
    cudaGetSymbolAddress((void**)&wt2, g_WT2);

    cudaFuncSetAttribute(gemm_mma_kernel, cudaFuncAttributeMaxDynamicSharedMemorySize,
                         GEMM_SMEM_BYTES);

    // 0) Pre-round / pre-transpose operands
    round_tf32_kernel<<<(BT_ * C_) / (256 * 4), 256>>>(x, xr);
    transpose_tf32_kernel<<<dim3(C3_ / 32, C_ / 32), dim3(32, 8)>>>(W_attn, wt1, C_, C3_);
    transpose_tf32_kernel<<<dim3(C_ / 32, C_ / 32), dim3(32, 8)>>>(W_proj, wt2, C_, C_);

    // 1) QKV projection (output tf32-rounded for attention)
    gemm_mma_kernel<<<dim3(C3_ / 128, BT_ / 128), 256, GEMM_SMEM_BYTES>>>(
        xr, wt1, b_attn, qkv_ptr, BT_, C3_, C_, 1);

    // 2) Causal flash attention (tensor cores, pipelined)
    attn_mma_kernel<<<dim3(T_ / 64, H_, B_), 128>>>(amask);

    // 3) Output projection (fp32 output)
    gemm_mma_kernel<<<dim3(C_ / 128, BT_ / 128), 256, GEMM_SMEM_BYTES>>>(
        y_ptr, wt2, b_proj, out, BT_, C_, C_, 0);
}

// round 9
// speedup vs baseline: 1.0861x; 1.0764x over previous
#include <cuda_runtime.h>
#include <cstdint>
#include <math.h>

// Problem constants
#define B_  2
#define T_  2048
#define C_  1024
#define H_  16
#define D_  64
#define BT_ (B_*T_)          // 4096
#define C3_ (3*C_)           // 3072

// Scratch (device globals: allocation-guard safe)
__device__ float g_qkv[BT_ * C3_];   // (B*T, 3C), stored tf32-rounded
__device__ float g_y[BT_ * C_];      // (B*T, C), stored tf32-rounded
__device__ float g_xr[BT_ * C_];     // x, tf32-rounded
__device__ float g_WT1[C3_ * C_];    // W_attn^T, tf32-rounded
__device__ float g_WT2[C_ * C_];     // W_proj^T, tf32-rounded

__device__ __forceinline__ float to_tf32(float f) {
    uint32_t u;
    asm("cvt.rna.tf32.f32 %0, %1;" : "=r"(u) : "f"(f));
    return __uint_as_float(u);
}

__device__ __forceinline__ void mma_tf32(float* d, const uint32_t* a, const uint32_t* b) {
    asm volatile(
        "mma.sync.aligned.m16n8k8.row.col.f32.tf32.tf32.f32 "
        "{%0,%1,%2,%3}, {%4,%5,%6,%7}, {%8,%9}, {%0,%1,%2,%3};"
        : "+f"(d[0]), "+f"(d[1]), "+f"(d[2]), "+f"(d[3])
        : "r"(a[0]), "r"(a[1]), "r"(a[2]), "r"(a[3]), "r"(b[0]), "r"(b[1]));
}

__device__ __forceinline__ uint32_t smem_u32(const void* p) {
    uint32_t a;
    asm("{ .reg .u64 t; cvta.to.shared.u64 t, %1; cvt.u32.u64 %0, t; }" : "=r"(a) : "l"(p));
    return a;
}
__device__ __forceinline__ void cp_async16(uint32_t saddr, const void* g) {
    asm volatile("cp.async.cg.shared.global [%0], [%1], 16;" :: "r"(saddr), "l"(g));
}
#define CP_COMMIT()  asm volatile("cp.async.commit_group;" ::: "memory")
#define CP_WAIT(n)   asm volatile("cp.async.wait_group %0;" :: "n"(n) : "memory")

// ============================================================================
// Elementwise tf32 rounding (vectorized): out[i] = tf32(in[i])
// ============================================================================
__global__ void round_tf32_kernel(const float* __restrict__ in, float* __restrict__ out)
{
    const int i = (blockIdx.x * blockDim.x + threadIdx.x) * 4;
    float4 v = *(const float4*)&in[i];
    v.x = to_tf32(v.x); v.y = to_tf32(v.y);
    v.z = to_tf32(v.z); v.w = to_tf32(v.w);
    *(float4*)&out[i] = v;
}

// ============================================================================
// Transpose + tf32-round: out[n][k] = tf32(in[k][n]).
// ============================================================================
__global__ void transpose_tf32_kernel(const float* __restrict__ in, float* __restrict__ out,
                                      int R, int Cc)
{
    __shared__ float tile[32][33];
    const int bx = blockIdx.x * 32;
    const int by = blockIdx.y * 32;
    #pragma unroll
    for (int j = 0; j < 32; j += 8)
        tile[threadIdx.y + j][threadIdx.x] = in[(size_t)(by + threadIdx.y + j) * Cc + bx + threadIdx.x];
    __syncthreads();
    #pragma unroll
    for (int j = 0; j < 32; j += 8)
        out[(size_t)(bx + threadIdx.y + j) * R + by + threadIdx.x] =
            to_tf32(tile[threadIdx.x][threadIdx.y + j]);
}

// ============================================================================
// tf32 mma.sync GEMM:  Cmat[M,N] = A[M,K] @ BT[N,K]^T + bias[N]
// Operands pre-rounded to tf32. Register double-buffer (R5 scheme):
// LDG for chunk ic+1 issued before compute of chunk ic; STS + one sync after.
// Block 128x128, BK=16, 256 threads (8 warps, 64x32 warp tiles).
// Smem layout [kq][row][4]: all accesses bank-conflict-free.
// ============================================================================
__global__ __launch_bounds__(256, 2) void gemm_mma_kernel(
    const float* __restrict__ A, const float* __restrict__ BT,
    const float* __restrict__ bias, float* __restrict__ Cmat,
    int M, int N, int K, int roundOut)
{
    __shared__ float As[2][4][128][4];   // [buf][kq][row][ic]
    __shared__ float Bs[2][4][128][4];

    const int tid  = threadIdx.x;
    const int lane = tid & 31;
    const int warp = tid >> 5;
    const int wr = warp >> 2;            // 0..1 -> m offset wr*64
    const int wc = warp & 3;             // 0..3 -> n offset wc*32
    const int g  = lane >> 2;            // 0..7
    const int kc = lane & 3;             // 0..3

    const int m0 = blockIdx.y * 128;
    const int n0 = blockIdx.x * 128;

    const int lm  = tid >> 2;            // 0..63
    const int lkq = tid & 3;             // 0..3

    float acc[4][4][4];
    #pragma unroll
    for (int mf = 0; mf < 4; mf++)
        #pragma unroll
        for (int nf = 0; nf < 4; nf++)
            #pragma unroll
            for (int r = 0; r < 4; r++) acc[mf][nf][r] = 0.f;

    const int nch = K >> 4;              // K/16

    // ---- prologue: chunk 0 -> buffer 0
    {
        #pragma unroll
        for (int it = 0; it < 2; it++) {
            const int m = lm + it * 64;
            *(float4*)&As[0][lkq][m][0] = *(const float4*)&A[(size_t)(m0 + m) * K + 4 * lkq];
            *(float4*)&Bs[0][lkq][m][0] = *(const float4*)&BT[(size_t)(n0 + m) * K + 4 * lkq];
        }
    }
    __syncthreads();

    for (int icn = 0; icn < nch; icn++) {
        const int cur = icn & 1;

        float4 pa[2], pb[2];
        const bool more = (icn + 1) < nch;
        if (more) {
            const int k0 = (icn + 1) << 4;
            #pragma unroll
            for (int it = 0; it < 2; it++) {
                const int m = lm + it * 64;
                pa[it] = *(const float4*)&A[(size_t)(m0 + m) * K + k0 + 4 * lkq];
                pb[it] = *(const float4*)&BT[(size_t)(n0 + m) * K + k0 + 4 * lkq];
            }
        }

        // compute on buffer cur
        #pragma unroll
        for (int t = 0; t < 2; t++) {
            uint32_t bf[4][2];
            #pragma unroll
            for (int nf = 0; nf < 4; nf++) {
                const int n = wc * 32 + nf * 8 + g;
                bf[nf][0] = __float_as_uint(Bs[cur][2 * t + 0][n][kc]);
                bf[nf][1] = __float_as_uint(Bs[cur][2 * t + 1][n][kc]);
            }
            #pragma unroll
            for (int mf = 0; mf < 4; mf++) {
                const int m = wr * 64 + mf * 16 + g;
                uint32_t af[4];
                af[0] = __float_as_uint(As[cur][2 * t + 0][m][kc]);
                af[1] = __float_as_uint(As[cur][2 * t + 0][m + 8][kc]);
                af[2] = __float_as_uint(As[cur][2 * t + 1][m][kc]);
                af[3] = __float_as_uint(As[cur][2 * t + 1][m + 8][kc]);
                #pragma unroll
                for (int nf = 0; nf < 4; nf++)
                    mma_tf32(acc[mf][nf], af, bf[nf]);
            }
        }

        if (more) {
            const int nxt = cur ^ 1;
            #pragma unroll
            for (int it = 0; it < 2; it++) {
                const int m = lm + it * 64;
                *(float4*)&As[nxt][lkq][m][0] = pa[it];
                *(float4*)&Bs[nxt][lkq][m][0] = pb[it];
            }
            __syncthreads();
        }
    }

    // ---- epilogue: acc -> gmem with bias
    #pragma unroll
    for (int mf = 0; mf < 4; mf++) {
        const int row = m0 + wr * 64 + mf * 16 + g;
        #pragma unroll
        for (int nf = 0; nf < 4; nf++) {
            const int col = n0 + wc * 32 + nf * 8 + kc * 2;
            const float b0 = bias[col];
            const float b1 = bias[col + 1];
            float2 o0 = { acc[mf][nf][0] + b0, acc[mf][nf][1] + b1 };
            float2 o1 = { acc[mf][nf][2] + b0, acc[mf][nf][3] + b1 };
            if (roundOut) {
                o0.x = to_tf32(o0.x); o0.y = to_tf32(o0.y);
                o1.x = to_tf32(o1.x); o1.y = to_tf32(o1.y);
            }
            *(float2*)&Cmat[(size_t)row * N + col] = o0;
            *(float2*)&Cmat[(size_t)(row + 8) * N + col] = o1;
        }
    }
}

// ============================================================================
// Flash attention (causal), tf32 mma.sync, cp.async double-buffered K/V.
// Inputs in g_qkv are already tf32-rounded -> no cvt in the mainloop.
// ============================================================================
#define KS_STRIDE 68
#define VS_STRIDE 72
#define PS_STRIDE 36

__global__ __launch_bounds__(128) void attn_mma_kernel(const float* __restrict__ amask)
{
    __shared__ __align__(16) float Ks[2][32 * KS_STRIDE];
    __shared__ __align__(16) float Vs[2][32 * VS_STRIDE];
    __shared__ __align__(16) float Ps[64 * PS_STRIDE];
    __shared__ float Ams[2][32];

    const int qt = (gridDim.x - 1) - blockIdx.x;   // heavy CTAs first
    const int hh = blockIdx.y;
    const int bb = blockIdx.z;
    const int tid = threadIdx.x;
    const int lane = tid & 31;
    const int w = tid >> 5;
    const int r = lane >> 2;
    const int c = lane & 3;
    const int qbase = qt * 64;
    const int qlo = qbase + w * 16;

    const uint32_t ksb = smem_u32(&Ks[0][0]);
    const uint32_t vsb = smem_u32(&Vs[0][0]);

    // --- stage Q into the Ks region (values already tf32) ---
    float* Qstage = &Ks[0][0];
    for (int i = tid; i < 64 * 16; i += 128) {
        const int row = i >> 4;
        const int c4 = (i & 15) * 4;
        float4 v = *(const float4*)&g_qkv[(size_t)(bb * T_ + qbase + row) * C3_ + hh * D_ + c4];
        *(float4*)&Qstage[row * KS_STRIDE + c4] = v;
    }
    __syncthreads();

    uint32_t qa[8][4];
    #pragma unroll
    for (int kf = 0; kf < 8; kf++) {
        const int row = w * 16 + r;
        const int col = kf * 8 + c;
        qa[kf][0] = __float_as_uint(Qstage[row * KS_STRIDE + col]);
        qa[kf][1] = __float_as_uint(Qstage[(row + 8) * KS_STRIDE + col]);
        qa[kf][2] = __float_as_uint(Qstage[row * KS_STRIDE + col + 4]);
        qa[kf][3] = __float_as_uint(Qstage[(row + 8) * KS_STRIDE + col + 4]);
    }
    __syncthreads();

    const int nkt = 2 * qt + 2;

    // --- prologue: tile 0 -> buf 0 ---
    {
        const size_t rb = (size_t)(bb * T_) * C3_ + hh * D_;
        for (int idx = tid; idx < 512; idx += 128) {
            const int row = idx >> 4;
            const int c4 = (idx & 15) * 4;
            const float* gk = &g_qkv[rb + (size_t)row * C3_ + C_ + c4];
            cp_async16(ksb + (uint32_t)(row * KS_STRIDE + c4) * 4u, gk);
            cp_async16(vsb + (uint32_t)(row * VS_STRIDE + c4) * 4u, gk + C_);
        }
        if (tid < 32) Ams[0][tid] = amask[bb * T_ + tid];
        CP_COMMIT();
    }

    float o[8][4];
    #pragma unroll
    for (int nb = 0; nb < 8; nb++)
        #pragma unroll
        for (int j = 0; j < 4; j++) o[nb][j] = 0.f;
    float mrow[2] = { -INFINITY, -INFINITY };
    float lrow[2] = { 0.f, 0.f };

    for (int kt = 0; kt < nkt; kt++) {
        const int buf = kt & 1;
        const int kbase = kt * 32;
        const bool more = (kt + 1) < nkt;

        if (more) {
            const int nb2 = buf ^ 1;
            const size_t rb = (size_t)(bb * T_ + kbase + 32) * C3_ + hh * D_;
            const uint32_t kdst = ksb + (uint32_t)(nb2 * 32 * KS_STRIDE) * 4u;
            const uint32_t vdst = vsb + (uint32_t)(nb2 * 32 * VS_STRIDE) * 4u;
            for (int idx = tid; idx < 512; idx += 128) {
                const int row = idx >> 4;
                const int c4 = (idx & 15) * 4;
                const float* gk = &g_qkv[rb + (size_t)row * C3_ + C_ + c4];
                cp_async16(kdst + (uint32_t)(row * KS_STRIDE + c4) * 4u, gk);
                cp_async16(vdst + (uint32_t)(row * VS_STRIDE + c4) * 4u, gk + C_);
            }
            if (tid < 32) Ams[nb2][tid] = amask[bb * T_ + kbase + 32 + tid];
            CP_COMMIT();
            CP_WAIT(1);
        } else {
            CP_WAIT(0);
        }
        __syncthreads();

        const bool act = (kbase <= qlo + 15);
        if (act) {
            const float* ksB = &Ks[buf][0];
            const float* vsB = &Vs[buf][0];

            // --- S = Q K^T ---
            float s[4][4];
            #pragma unroll
            for (int nb = 0; nb < 4; nb++)
                #pragma unroll
                for (int j = 0; j < 4; j++) s[nb][j] = 0.f;
            #pragma unroll
            for (int kf = 0; kf < 8; kf++) {
                #pragma unroll
                for (int nb = 0; nb < 4; nb++) {
                    uint32_t bf[2];
                    bf[0] = __float_as_uint(ksB[(nb * 8 + r) * KS_STRIDE + kf * 8 + c]);
                    bf[1] = __float_as_uint(ksB[(nb * 8 + r) * KS_STRIDE + kf * 8 + c + 4]);
                    mma_tf32(s[nb], qa[kf], bf);
                }
            }

            // --- scale + masks ---
            const bool needmask = (kbase + 31 > qlo);
            #pragma unroll
            for (int nb = 0; nb < 4; nb++) {
                const float a0 = Ams[buf][nb * 8 + 2 * c];
                const float a1 = Ams[buf][nb * 8 + 2 * c + 1];
                s[nb][0] = s[nb][0] * 0.125f + a0;
                s[nb][1] = s[nb][1] * 0.125f + a1;
                s[nb][2] = s[nb][2] * 0.125f + a0;
                s[nb][3] = s[nb][3] * 0.125f + a1;
                if (needmask) {
                    const int kc0 = kbase + nb * 8 + 2 * c;
                    const int q0 = qlo + r;
                    if (kc0 > q0)         s[nb][0] = -INFINITY;
                    if (kc0 + 1 > q0)     s[nb][1] = -INFINITY;
                    if (kc0 > q0 + 8)     s[nb][2] = -INFINITY;
                    if (kc0 + 1 > q0 + 8) s[nb][3] = -INFINITY;
                }
            }

            __syncwarp();

            // --- online softmax ---
            #pragma unroll
            for (int hf = 0; hf < 2; hf++) {
                float mx = -INFINITY;
                #pragma unroll
                for (int nb = 0; nb < 4; nb++)
                    mx = fmaxf(mx, fmaxf(s[nb][2 * hf], s[nb][2 * hf + 1]));
                mx = fmaxf(mx, __shfl_xor_sync(0xffffffffu, mx, 1));
                mx = fmaxf(mx, __shfl_xor_sync(0xffffffffu, mx, 2));
                const float mnew = fmaxf(mrow[hf], mx);
                const float corr = __expf(mrow[hf] - mnew);
                float sum = 0.f;
                const int prow = w * 16 + r + 8 * hf;
                #pragma unroll
                for (int nb = 0; nb < 4; nb++) {
                    const float p0 = __expf(s[nb][2 * hf] - mnew);
                    const float p1 = __expf(s[nb][2 * hf + 1] - mnew);
                    sum += p0 + p1;
                    Ps[prow * PS_STRIDE + nb * 8 + 2 * c]     = to_tf32(p0);
                    Ps[prow * PS_STRIDE + nb * 8 + 2 * c + 1] = to_tf32(p1);
                }
                sum += __shfl_xor_sync(0xffffffffu, sum, 1);
                sum += __shfl_xor_sync(0xffffffffu, sum, 2);
                lrow[hf] = lrow[hf] * corr + sum;
                mrow[hf] = mnew;
                #pragma unroll
                for (int nb = 0; nb < 8; nb++) {
                    o[nb][2 * hf]     *= corr;
                    o[nb][2 * hf + 1] *= corr;
                }
            }
            __syncwarp();

            // --- O += P V ---
            #pragma unroll
            for (int kf = 0; kf < 4; kf++) {
                uint32_t pa[4];
                const int prow = w * 16 + r;
                pa[0] = __float_as_uint(Ps[prow * PS_STRIDE + kf * 8 + c]);
                pa[1] = __float_as_uint(Ps[(prow + 8) * PS_STRIDE + kf * 8 + c]);
                pa[2] = __float_as_uint(Ps[prow * PS_STRIDE + kf * 8 + c + 4]);
                pa[3] = __float_as_uint(Ps[(prow + 8) * PS_STRIDE + kf * 8 + c + 4]);
                #pragma unroll
                for (int nb = 0; nb < 8; nb++) {
                    uint32_t bf[2];
                    bf[0] = __float_as_uint(vsB[(kf * 8 + c) * VS_STRIDE + nb * 8 + r]);
                    bf[1] = __float_as_uint(vsB[(kf * 8 + c + 4) * VS_STRIDE + nb * 8 + r]);
                    mma_tf32(o[nb], pa, bf);
                }
            }
        }
        __syncthreads();
    }

    // --- epilogue: write g_y tf32-rounded (proj GEMM reads it pre-rounded) ---
    const float inv0 = 1.f / lrow[0];
    const float inv1 = 1.f / lrow[1];
    const int row0 = bb * T_ + qbase + w * 16 + r;
    #pragma unroll
    for (int nb = 0; nb < 8; nb++) {
        const int col = hh * D_ + nb * 8 + 2 * c;
        float2 v0 = { to_tf32(o[nb][0] * inv0), to_tf32(o[nb][1] * inv0) };
        float2 v1 = { to_tf32(o[nb][2] * inv1), to_tf32(o[nb][3] * inv1) };
        *(float2*)&g_y[(size_t)row0 * C_ + col] = v0;
        *(float2*)&g_y[(size_t)(row0 + 8) * C_ + col] = v1;
    }
}

// ----------------------------------------------------------------------------
// Launch.  Inputs: 0 x, 1 attention_mask, 2 attention_bias, 3 W_attn,
//                  4 b_attn, 5 W_proj, 6 b_proj
// ----------------------------------------------------------------------------
extern "C" void kernel_launch(void* const* d_in, const int* in_sizes, int n_in,
                              void* d_out, int out_size)
{
    (void)in_sizes; (void)n_in; (void)out_size;
    const float* x      = (const float*)d_in[0];
    const float* amask  = (const float*)d_in[1];
    const float* W_attn = (const float*)d_in[3];
    const float* b_attn = (const float*)d_in[4];
    const float* W_proj = (const float*)d_in[5];
    const float* b_proj = (const float*)d_in[6];
    float* out = (float*)d_out;

    float *qkv_ptr = nullptr, *y_ptr = nullptr, *xr = nullptr, *wt1 = nullptr, *wt2 = nullptr;
    cudaGetSymbolAddress((void**)&qkv_ptr, g_qkv);
    cudaGetSymbolAddress((void**)&y_ptr, g_y);
    cudaGetSymbolAddress((void**)&xr, g_xr);
    cudaGetSymbolAddress((void**)&wt1, g_WT1);
    cudaGetSymbolAddress((void**)&wt2, g_WT2);

    // 0) Pre-round / pre-transpose operands
    round_tf32_kernel<<<(BT_ * C_) / (256 * 4), 256>>>(x, xr);
    transpose_tf32_kernel<<<dim3(C3_ / 32, C_ / 32), dim3(32, 8)>>>(W_attn, wt1, C_, C3_);
    transpose_tf32_kernel<<<dim3(C_ / 32, C_ / 32), dim3(32, 8)>>>(W_proj, wt2, C_, C_);

    // 1) QKV projection (output tf32-rounded for attention)
    gemm_mma_kernel<<<dim3(C3_ / 128, BT_ / 128), 256>>>(xr, wt1, b_attn, qkv_ptr, BT_, C3_, C_, 1);

    // 2) Causal flash attention (tensor cores, pipelined)
    attn_mma_kernel<<<dim3(T_ / 64, H_, B_), 128>>>(amask);

    // 3) Output projection (fp32 output)
    gemm_mma_kernel<<<dim3(C_ / 128, BT_ / 128), 256>>>(y_ptr, wt2, b_proj, out, BT_, C_, C_, 0);
}

// round 10
// speedup vs baseline: 1.1047x; 1.0172x over previous
#include <cuda_runtime.h>
#include <cstdint>
#include <math.h>

// Problem constants
#define B_  2
#define T_  2048
#define C_  1024
#define H_  16
#define D_  64
#define BT_ (B_*T_)          // 4096
#define C3_ (3*C_)           // 3072

// Scratch (device globals: allocation-guard safe)
__device__ float g_qkv[BT_ * C3_];   // (B*T, 3C), stored tf32-rounded
__device__ float g_y[BT_ * C_];      // (B*T, C), stored tf32-rounded
__device__ float g_xr[BT_ * C_];     // x, tf32-rounded
__device__ float g_WT1[C3_ * C_];    // W_attn^T, tf32-rounded
__device__ float g_WT2[C_ * C_];     // W_proj^T, tf32-rounded

__device__ __forceinline__ float to_tf32(float f) {
    uint32_t u;
    asm("cvt.rna.tf32.f32 %0, %1;" : "=r"(u) : "f"(f));
    return __uint_as_float(u);
}

__device__ __forceinline__ void mma_tf32(float* d, const uint32_t* a, const uint32_t* b) {
    asm volatile(
        "mma.sync.aligned.m16n8k8.row.col.f32.tf32.tf32.f32 "
        "{%0,%1,%2,%3}, {%4,%5,%6,%7}, {%8,%9}, {%0,%1,%2,%3};"
        : "+f"(d[0]), "+f"(d[1]), "+f"(d[2]), "+f"(d[3])
        : "r"(a[0]), "r"(a[1]), "r"(a[2]), "r"(a[3]), "r"(b[0]), "r"(b[1]));
}

__device__ __forceinline__ uint32_t smem_u32(const void* p) {
    uint32_t a;
    asm("{ .reg .u64 t; cvta.to.shared.u64 t, %1; cvt.u32.u64 %0, t; }" : "=r"(a) : "l"(p));
    return a;
}
__device__ __forceinline__ void cp_async16(uint32_t saddr, const void* g) {
    asm volatile("cp.async.cg.shared.global [%0], [%1], 16;" :: "r"(saddr), "l"(g));
}
#define CP_COMMIT()  asm volatile("cp.async.commit_group;" ::: "memory")
#define CP_WAIT(n)   asm volatile("cp.async.wait_group %0;" :: "n"(n) : "memory")

// ============================================================================
// Elementwise tf32 rounding (vectorized): out[i] = tf32(in[i])
// ============================================================================
__global__ void round_tf32_kernel(const float* __restrict__ in, float* __restrict__ out)
{
    const int i = (blockIdx.x * blockDim.x + threadIdx.x) * 4;
    float4 v = *(const float4*)&in[i];
    v.x = to_tf32(v.x); v.y = to_tf32(v.y);
    v.z = to_tf32(v.z); v.w = to_tf32(v.w);
    *(float4*)&out[i] = v;
}

// ============================================================================
// Transpose + tf32-round: out[n][k] = tf32(in[k][n]).
// ============================================================================
__global__ void transpose_tf32_kernel(const float* __restrict__ in, float* __restrict__ out,
                                      int R, int Cc)
{
    __shared__ float tile[32][33];
    const int bx = blockIdx.x * 32;
    const int by = blockIdx.y * 32;
    #pragma unroll
    for (int j = 0; j < 32; j += 8)
        tile[threadIdx.y + j][threadIdx.x] = in[(size_t)(by + threadIdx.y + j) * Cc + bx + threadIdx.x];
    __syncthreads();
    #pragma unroll
    for (int j = 0; j < 32; j += 8)
        out[(size_t)(bx + threadIdx.y + j) * R + by + threadIdx.x] =
            to_tf32(tile[threadIdx.x][threadIdx.y + j]);
}

// ============================================================================
// tf32 mma.sync GEMM:  Cmat[M,N] = A[M,K] @ BT[N,K]^T + bias[N]
// Operands pre-rounded to tf32. Register double-buffer, BK=16.
// CTA tile 256x128, 256 threads = 8 warps as 4(m) x 2(n), warp tile 64x64.
// Smem layout [kq][row][4]: all accesses bank-conflict-free.
// ============================================================================
__global__ __launch_bounds__(256, 1) void gemm_mma_kernel(
    const float* __restrict__ A, const float* __restrict__ BT,
    const float* __restrict__ bias, float* __restrict__ Cmat,
    int M, int N, int K, int roundOut)
{
    __shared__ float As[2][4][256][4];   // [buf][kq][row][ic]  32KB
    __shared__ float Bs[2][4][128][4];   // 16KB

    const int tid  = threadIdx.x;
    const int lane = tid & 31;
    const int warp = tid >> 5;
    const int wr = warp >> 1;            // 0..3 -> m offset wr*64
    const int wc = warp & 1;             // 0..1 -> n offset wc*64
    const int g  = lane >> 2;            // 0..7
    const int kc = lane & 3;             // 0..3

    const int m0 = blockIdx.y * 256;
    const int n0 = blockIdx.x * 128;

    const int lm  = tid >> 2;            // 0..63
    const int lkq = tid & 3;             // 0..3

    float acc[4][8][4];
    #pragma unroll
    for (int mf = 0; mf < 4; mf++)
        #pragma unroll
        for (int nf = 0; nf < 8; nf++)
            #pragma unroll
            for (int r = 0; r < 4; r++) acc[mf][nf][r] = 0.f;

    const int nch = K >> 4;              // K/16

    // ---- prologue: chunk 0 -> buffer 0 (A: 4 rows/thread, B: 2 rows/thread)
    {
        #pragma unroll
        for (int it = 0; it < 4; it++) {
            const int m = lm + it * 64;
            *(float4*)&As[0][lkq][m][0] = *(const float4*)&A[(size_t)(m0 + m) * K + 4 * lkq];
        }
        #pragma unroll
        for (int it = 0; it < 2; it++) {
            const int n = lm + it * 64;
            *(float4*)&Bs[0][lkq][n][0] = *(const float4*)&BT[(size_t)(n0 + n) * K + 4 * lkq];
        }
    }
    __syncthreads();

    for (int icn = 0; icn < nch; icn++) {
        const int cur = icn & 1;

        float4 pa[4], pb[2];
        const bool more = (icn + 1) < nch;
        if (more) {
            const int k0 = (icn + 1) << 4;
            #pragma unroll
            for (int it = 0; it < 4; it++) {
                const int m = lm + it * 64;
                pa[it] = *(const float4*)&A[(size_t)(m0 + m) * K + k0 + 4 * lkq];
            }
            #pragma unroll
            for (int it = 0; it < 2; it++) {
                const int n = lm + it * 64;
                pb[it] = *(const float4*)&BT[(size_t)(n0 + n) * K + k0 + 4 * lkq];
            }
        }

        // compute on buffer cur: warp tile 64x64, two k8 steps per t
        #pragma unroll
        for (int t = 0; t < 2; t++) {
            uint32_t bf[8][2];
            #pragma unroll
            for (int nf = 0; nf < 8; nf++) {
                const int n = wc * 64 + nf * 8 + g;
                bf[nf][0] = __float_as_uint(Bs[cur][2 * t + 0][n][kc]);
                bf[nf][1] = __float_as_uint(Bs[cur][2 * t + 1][n][kc]);
            }
            #pragma unroll
            for (int mf = 0; mf < 4; mf++) {
                const int m = wr * 64 + mf * 16 + g;
                uint32_t af[4];
                af[0] = __float_as_uint(As[cur][2 * t + 0][m][kc]);
                af[1] = __float_as_uint(As[cur][2 * t + 0][m + 8][kc]);
                af[2] = __float_as_uint(As[cur][2 * t + 1][m][kc]);
                af[3] = __float_as_uint(As[cur][2 * t + 1][m + 8][kc]);
                #pragma unroll
                for (int nf = 0; nf < 8; nf++)
                    mma_tf32(acc[mf][nf], af, bf[nf]);
            }
        }

        if (more) {
            const int nxt = cur ^ 1;
            #pragma unroll
            for (int it = 0; it < 4; it++) {
                const int m = lm + it * 64;
                *(float4*)&As[nxt][lkq][m][0] = pa[it];
            }
            #pragma unroll
            for (int it = 0; it < 2; it++) {
                const int n = lm + it * 64;
                *(float4*)&Bs[nxt][lkq][n][0] = pb[it];
            }
            __syncthreads();
        }
    }

    // ---- epilogue: acc -> gmem with bias
    #pragma unroll
    for (int mf = 0; mf < 4; mf++) {
        const int row = m0 + wr * 64 + mf * 16 + g;
        #pragma unroll
        for (int nf = 0; nf < 8; nf++) {
            const int col = n0 + wc * 64 + nf * 8 + kc * 2;
            const float b0 = bias[col];
            const float b1 = bias[col + 1];
            float2 o0 = { acc[mf][nf][0] + b0, acc[mf][nf][1] + b1 };
            float2 o1 = { acc[mf][nf][2] + b0, acc[mf][nf][3] + b1 };
            if (roundOut) {
                o0.x = to_tf32(o0.x); o0.y = to_tf32(o0.y);
                o1.x = to_tf32(o1.x); o1.y = to_tf32(o1.y);
            }
            *(float2*)&Cmat[(size_t)row * N + col] = o0;
            *(float2*)&Cmat[(size_t)(row + 8) * N + col] = o1;
        }
    }
}

// ============================================================================
// Flash attention (causal), tf32 mma.sync, cp.async double-buffered K/V.
// Inputs in g_qkv are already tf32-rounded -> no cvt in the mainloop.
// ============================================================================
#define KS_STRIDE 68
#define VS_STRIDE 72
#define PS_STRIDE 36

__global__ __launch_bounds__(128) void attn_mma_kernel(const float* __restrict__ amask)
{
    __shared__ __align__(16) float Ks[2][32 * KS_STRIDE];
    __shared__ __align__(16) float Vs[2][32 * VS_STRIDE];
    __shared__ __align__(16) float Ps[64 * PS_STRIDE];
    __shared__ float Ams[2][32];

    const int qt = (gridDim.x - 1) - blockIdx.x;   // heavy CTAs first
    const int hh = blockIdx.y;
    const int bb = blockIdx.z;
    const int tid = threadIdx.x;
    const int lane = tid & 31;
    const int w = tid >> 5;
    const int r = lane >> 2;
    const int c = lane & 3;
    const int qbase = qt * 64;
    const int qlo = qbase + w * 16;

    const uint32_t ksb = smem_u32(&Ks[0][0]);
    const uint32_t vsb = smem_u32(&Vs[0][0]);

    // --- stage Q into the Ks region (values already tf32) ---
    float* Qstage = &Ks[0][0];
    for (int i = tid; i < 64 * 16; i += 128) {
        const int row = i >> 4;
        const int c4 = (i & 15) * 4;
        float4 v = *(const float4*)&g_qkv[(size_t)(bb * T_ + qbase + row) * C3_ + hh * D_ + c4];
        *(float4*)&Qstage[row * KS_STRIDE + c4] = v;
    }
    __syncthreads();

    uint32_t qa[8][4];
    #pragma unroll
    for (int kf = 0; kf < 8; kf++) {
        const int row = w * 16 + r;
        const int col = kf * 8 + c;
        qa[kf][0] = __float_as_uint(Qstage[row * KS_STRIDE + col]);
        qa[kf][1] = __float_as_uint(Qstage[(row + 8) * KS_STRIDE + col]);
        qa[kf][2] = __float_as_uint(Qstage[row * KS_STRIDE + col + 4]);
        qa[kf][3] = __float_as_uint(Qstage[(row + 8) * KS_STRIDE + col + 4]);
    }
    __syncthreads();

    const int nkt = 2 * qt + 2;

    // --- prologue: tile 0 -> buf 0 ---
    {
        const size_t rb = (size_t)(bb * T_) * C3_ + hh * D_;
        for (int idx = tid; idx < 512; idx += 128) {
            const int row = idx >> 4;
            const int c4 = (idx & 15) * 4;
            const float* gk = &g_qkv[rb + (size_t)row * C3_ + C_ + c4];
            cp_async16(ksb + (uint32_t)(row * KS_STRIDE + c4) * 4u, gk);
            cp_async16(vsb + (uint32_t)(row * VS_STRIDE + c4) * 4u, gk + C_);
        }
        if (tid < 32) Ams[0][tid] = amask[bb * T_ + tid];
        CP_COMMIT();
    }

    float o[8][4];
    #pragma unroll
    for (int nb = 0; nb < 8; nb++)
        #pragma unroll
        for (int j = 0; j < 4; j++) o[nb][j] = 0.f;
    float mrow[2] = { -INFINITY, -INFINITY };
    float lrow[2] = { 0.f, 0.f };

    for (int kt = 0; kt < nkt; kt++) {
        const int buf = kt & 1;
        const int kbase = kt * 32;
        const bool more = (kt + 1) < nkt;

        if (more) {
            const int nb2 = buf ^ 1;
            const size_t rb = (size_t)(bb * T_ + kbase + 32) * C3_ + hh * D_;
            const uint32_t kdst = ksb + (uint32_t)(nb2 * 32 * KS_STRIDE) * 4u;
            const uint32_t vdst = vsb + (uint32_t)(nb2 * 32 * VS_STRIDE) * 4u;
            for (int idx = tid; idx < 512; idx += 128) {
                const int row = idx >> 4;
                const int c4 = (idx & 15) * 4;
                const float* gk = &g_qkv[rb + (size_t)row * C3_ + C_ + c4];
                cp_async16(kdst + (uint32_t)(row * KS_STRIDE + c4) * 4u, gk);
                cp_async16(vdst + (uint32_t)(row * VS_STRIDE + c4) * 4u, gk + C_);
            }
            if (tid < 32) Ams[nb2][tid] = amask[bb * T_ + kbase + 32 + tid];
            CP_COMMIT();
            CP_WAIT(1);
        } else {
            CP_WAIT(0);
        }
        __syncthreads();

        const bool act = (kbase <= qlo + 15);
        if (act) {
            const float* ksB = &Ks[buf][0];
            const float* vsB = &Vs[buf][0];

            // --- S = Q K^T ---
            float s[4][4];
            #pragma unroll
            for (int nb = 0; nb < 4; nb++)
                #pragma unroll
                for (int j = 0; j < 4; j++) s[nb][j] = 0.f;
            #pragma unroll
            for (int kf = 0; kf < 8; kf++) {
                #pragma unroll
                for (int nb = 0; nb < 4; nb++) {
                    uint32_t bf[2];
                    bf[0] = __float_as_uint(ksB[(nb * 8 + r) * KS_STRIDE + kf * 8 + c]);
                    bf[1] = __float_as_uint(ksB[(nb * 8 + r) * KS_STRIDE + kf * 8 + c + 4]);
                    mma_tf32(s[nb], qa[kf], bf);
                }
            }

            // --- scale + masks ---
            const bool needmask = (kbase + 31 > qlo);
            #pragma unroll
            for (int nb = 0; nb < 4; nb++) {
                const float a0 = Ams[buf][nb * 8 + 2 * c];
                const float a1 = Ams[buf][nb * 8 + 2 * c + 1];
                s[nb][0] = s[nb][0] * 0.125f + a0;
                s[nb][1] = s[nb][1] * 0.125f + a1;
                s[nb][2] = s[nb][2] * 0.125f + a0;
                s[nb][3] = s[nb][3] * 0.125f + a1;
                if (needmask) {
                    const int kc0 = kbase + nb * 8 + 2 * c;
                    const int q0 = qlo + r;
                    if (kc0 > q0)         s[nb][0] = -INFINITY;
                    if (kc0 + 1 > q0)     s[nb][1] = -INFINITY;
                    if (kc0 > q0 + 8)     s[nb][2] = -INFINITY;
                    if (kc0 + 1 > q0 + 8) s[nb][3] = -INFINITY;
                }
            }

            __syncwarp();

            // --- online softmax ---
            #pragma unroll
            for (int hf = 0; hf < 2; hf++) {
                float mx = -INFINITY;
                #pragma unroll
                for (int nb = 0; nb < 4; nb++)
                    mx = fmaxf(mx, fmaxf(s[nb][2 * hf], s[nb][2 * hf + 1]));
                mx = fmaxf(mx, __shfl_xor_sync(0xffffffffu, mx, 1));
                mx = fmaxf(mx, __shfl_xor_sync(0xffffffffu, mx, 2));
                const float mnew = fmaxf(mrow[hf], mx);
                const float corr = __expf(mrow[hf] - mnew);
                float sum = 0.f;
                const int prow = w * 16 + r + 8 * hf;
                #pragma unroll
                for (int nb = 0; nb < 4; nb++) {
                    const float p0 = __expf(s[nb][2 * hf] - mnew);
                    const float p1 = __expf(s[nb][2 * hf + 1] - mnew);
                    sum += p0 + p1;
                    Ps[prow * PS_STRIDE + nb * 8 + 2 * c]     = to_tf32(p0);
                    Ps[prow * PS_STRIDE + nb * 8 + 2 * c + 1] = to_tf32(p1);
                }
                sum += __shfl_xor_sync(0xffffffffu, sum, 1);
                sum += __shfl_xor_sync(0xffffffffu, sum, 2);
                lrow[hf] = lrow[hf] * corr + sum;
                mrow[hf] = mnew;
                #pragma unroll
                for (int nb = 0; nb < 8; nb++) {
                    o[nb][2 * hf]     *= corr;
                    o[nb][2 * hf + 1] *= corr;
                }
            }
            __syncwarp();

            // --- O += P V ---
            #pragma unroll
            for (int kf = 0; kf < 4; kf++) {
                uint32_t pa[4];
                const int prow = w * 16 + r;
                pa[0] = __float_as_uint(Ps[prow * PS_STRIDE + kf * 8 + c]);
                pa[1] = __float_as_uint(Ps[(prow + 8) * PS_STRIDE + kf * 8 + c]);
                pa[2] = __float_as_uint(Ps[prow * PS_STRIDE + kf * 8 + c + 4]);
                pa[3] = __float_as_uint(Ps[(prow + 8) * PS_STRIDE + kf * 8 + c + 4]);
                #pragma unroll
                for (int nb = 0; nb < 8; nb++) {
                    uint32_t bf[2];
                    bf[0] = __float_as_uint(vsB[(kf * 8 + c) * VS_STRIDE + nb * 8 + r]);
                    bf[1] = __float_as_uint(vsB[(kf * 8 + c + 4) * VS_STRIDE + nb * 8 + r]);
                    mma_tf32(o[nb], pa, bf);
                }
            }
        }
        __syncthreads();
    }

    // --- epilogue: write g_y tf32-rounded (proj GEMM reads it pre-rounded) ---
    const float inv0 = 1.f / lrow[0];
    const float inv1 = 1.f / lrow[1];
    const int row0 = bb * T_ + qbase + w * 16 + r;
    #pragma unroll
    for (int nb = 0; nb < 8; nb++) {
        const int col = hh * D_ + nb * 8 + 2 * c;
        float2 v0 = { to_tf32(o[nb][0] * inv0), to_tf32(o[nb][1] * inv0) };
        float2 v1 = { to_tf32(o[nb][2] * inv1), to_tf32(o[nb][3] * inv1) };
        *(float2*)&g_y[(size_t)row0 * C_ + col] = v0;
        *(float2*)&g_y[(size_t)(row0 + 8) * C_ + col] = v1;
    }
}

// ----------------------------------------------------------------------------
// Launch.  Inputs: 0 x, 1 attention_mask, 2 attention_bias, 3 W_attn,
//                  4 b_attn, 5 W_proj, 6 b_proj
// ----------------------------------------------------------------------------
extern "C" void kernel_launch(void* const* d_in, const int* in_sizes, int n_in,
                              void* d_out, int out_size)
{
    (void)in_sizes; (void)n_in; (void)out_size;
    const float* x      = (const float*)d_in[0];
    const float* amask  = (const float*)d_in[1];
    const float* W_attn = (const float*)d_in[3];
    const float* b_attn = (const float*)d_in[4];
    const float* W_proj = (const float*)d_in[5];
    const float* b_proj = (const float*)d_in[6];
    float* out = (float*)d_out;

    float *qkv_ptr = nullptr, *y_ptr = nullptr, *xr = nullptr, *wt1 = nullptr, *wt2 = nullptr;
    cudaGetSymbolAddress((void**)&qkv_ptr, g_qkv);
    cudaGetSymbolAddress((void**)&y_ptr, g_y);
    cudaGetSymbolAddress((void**)&xr, g_xr);
    cudaGetSymbolAddress((void**)&wt1, g_WT1);
    cudaGetSymbolAddress((void**)&wt2, g_WT2);

    // 0) Pre-round / pre-transpose operands
    round_tf32_kernel<<<(BT_ * C_) / (256 * 4), 256>>>(x, xr);
    transpose_tf32_kernel<<<dim3(C3_ / 32, C_ / 32), dim3(32, 8)>>>(W_attn, wt1, C_, C3_);
    transpose_tf32_kernel<<<dim3(C_ / 32, C_ / 32), dim3(32, 8)>>>(W_proj, wt2, C_, C_);

    // 1) QKV projection (output tf32-rounded for attention): 16 x 24 CTAs
    gemm_mma_kernel<<<dim3(C3_ / 128, BT_ / 256), 256>>>(xr, wt1, b_attn, qkv_ptr, BT_, C3_, C_, 1);

    // 2) Causal flash attention (tensor cores, pipelined)
    attn_mma_kernel<<<dim3(T_ / 64, H_, B_), 128>>>(amask);

    // 3) Output projection (fp32 output): 16 x 8 CTAs
    gemm_mma_kernel<<<dim3(C_ / 128, BT_ / 256), 256>>>(y_ptr, wt2, b_proj, out, BT_, C_, C_, 0);
}